// round 12
// baseline (speedup 1.0000x reference)
#include <cuda_runtime.h>
#include <cuda_fp16.h>
#include <cstdint>

// GeometryOptimalTransport: sparse Sinkhorn attention. b=4, n=4096, d=64.
// R12: (1) sinkhorn_all at 2 blocks/SM (launch_bounds(1024,2), PBLK=64,
//          MLP-2 chunk pairs) -> occupancy 46% -> ~93%.
//      (2) final: 2-cell superblocks with 162KB smem V-cache, V rows
//          pre-scaled by ev[s] at staging -> no per-pair dual gather.

#define BB 4
#define NN 4096
#define DD 64
#define STRIDE 640            // max valid neighbors ~515+6sigma; multiple of 128
#define WPB 8
#define THREADS 256
#define NSLAB 16
#define NXBIN 16
#define NCELL2 16             // 16x16 target cells
#define TCAP2 64              // targets per cell cap (mean 16)
#define PBLK 64               // blocks per batch in the fused pass kernel
#define VCAP 1152             // halo V rows per superblock (mean ~995, +5.7sigma)
#define SENTINEL 0u           // K = 0, off = 0 -> contributes exactly 0

// log2(e) / (EPS + 1e-8), EPS = 0.01
__device__ __constant__ float C2 = (float)(1.4426950408889634 / 0.01000001);

__device__ uint32_t g_listT[BB * NN * STRIDE];   // entries: (f16 K)<<16 | idx<<2
__device__ uint32_t g_listS[BB * NN * STRIDE];
__device__ int g_cntT[BB * NN];                  // padded counts (multiple of 128)
__device__ int g_cntS[BB * NN];
__device__ float g_eu[BB * NN];
__device__ float g_ev[BB * NN];
// (yslab, xbin) sorted candidate arrays
__device__ float2 g_sortloc[2][BB][NN];
__device__ unsigned short g_sortid[2][BB][NN];
__device__ float2 g_loc2[2][BB][NN];
__device__ unsigned short g_id2[2][BB][NN];
__device__ int g_binstart[2][BB][NSLAB * NXBIN + 1];
// target cell lists
__device__ int g_tcnt[BB * NCELL2 * NCELL2];
__device__ int g_tlist[BB * NCELL2 * NCELL2][TCAP2];
// software barrier (g_arrive self-resets; g_phase monotone across replays)
__device__ int g_arrive[BB];
__device__ int g_phase[BB];

static __device__ __forceinline__ float ex2f(float x) {
    float y; asm("ex2.approx.ftz.f32 %0, %1;" : "=f"(y) : "f"(x)); return y;
}
static __device__ __forceinline__ float rcpf(float x) {
    float y; asm("rcp.approx.ftz.f32 %0, %1;" : "=f"(y) : "f"(x)); return y;
}
static __device__ __forceinline__ float gat(const float* s, uint32_t e) {
    return *reinterpret_cast<const float*>(
        reinterpret_cast<const char*>(s) + (e & 0xFFFCu));
}
static __device__ __forceinline__ float kof(uint32_t e) {
    return __half2float(__ushort_as_half((unsigned short)(e >> 16)));
}

// ---------------------------------------------------------------------------
// Merged y-slab + x-bin deterministic counting sort. Zeroes g_tcnt.
// ---------------------------------------------------------------------------
__global__ void slab_xbin(const float2* __restrict__ tlocs,
                          const float2* __restrict__ slocs)
{
    const int b = blockIdx.x, mode = blockIdx.y;
    const float2* cl = (mode ? tlocs : slocs) + (size_t)b * NN;
    __shared__ int s_cnt[NSLAB + 1];
    const int tid = threadIdx.x, wid = tid >> 5, lane = tid & 31;  // 16 warps

    if (blockIdx.x == 0 && blockIdx.y == 0)
        for (int k = tid; k < BB * NCELL2 * NCELL2; k += 512) g_tcnt[k] = 0;

    int c = 0;
    for (int i0 = 0; i0 < NN; i0 += 32) {
        const float2 p = cl[i0 + lane];
        const int sl = min(max((int)(p.y * (float)NSLAB), 0), NSLAB - 1);
        c += __popc(__ballot_sync(0xffffffffu, sl == wid));
    }
    if (lane == 0) s_cnt[wid + 1] = c;
    __syncthreads();
    if (tid == 0) {
        s_cnt[0] = 0;
        for (int k = 1; k <= NSLAB; k++) s_cnt[k] += s_cnt[k - 1];
    }
    __syncthreads();
    {
        int base = s_cnt[wid];
        for (int i0 = 0; i0 < NN; i0 += 32) {
            const float2 p = cl[i0 + lane];
            const int sl = min(max((int)(p.y * (float)NSLAB), 0), NSLAB - 1);
            const bool m = (sl == wid);
            const unsigned bal = __ballot_sync(0xffffffffu, m);
            if (m) {
                const int o = base + __popc(bal & ((1u << lane) - 1u));
                g_sortloc[mode][b][o] = p;
                g_sortid[mode][b][o] = (unsigned short)(i0 + lane);
            }
            base += __popc(bal);
        }
    }
    __syncthreads();

    const int beg = s_cnt[wid];
    const int end = s_cnt[wid + 1];
    int base = beg;
    for (int xb = 0; xb < NXBIN; xb++) {
        if (lane == 0) g_binstart[mode][b][wid * NXBIN + xb] = base;
        for (int i0 = beg; i0 < end; i0 += 32) {
            const int i = i0 + lane;
            bool m = false;
            float2 p; unsigned short id = 0;
            if (i < end) {
                p = g_sortloc[mode][b][i];
                id = g_sortid[mode][b][i];
                const int xbin = min(max((int)(p.x * (float)NXBIN), 0), NXBIN - 1);
                m = (xbin == xb);
            }
            const unsigned bal = __ballot_sync(0xffffffffu, m);
            if (m) {
                const int o = base + __popc(bal & ((1u << lane) - 1u));
                g_loc2[mode][b][o] = p;
                g_id2[mode][b][o] = id;
            }
            base += __popc(bal);
        }
    }
    if (wid == NSLAB - 1 && lane == 0)
        g_binstart[mode][b][NSLAB * NXBIN] = end;
}

// ---------------------------------------------------------------------------
// Bin targets into 16x16 cells.
// ---------------------------------------------------------------------------
__global__ void bin_targets(const float2* __restrict__ tlocs)
{
    const int i = blockIdx.x * THREADS + threadIdx.x;
    if (i >= BB * NN) return;
    const int b = i >> 12, t = i & (NN - 1);
    const float2 p = tlocs[i];
    const int cx = min(max((int)(p.x * (float)NCELL2), 0), NCELL2 - 1);
    const int cy = min(max((int)(p.y * (float)NCELL2), 0), NCELL2 - 1);
    const int cell = b * NCELL2 * NCELL2 + cy * NCELL2 + cx;
    const int pos = atomicAdd(&g_tcnt[cell], 1);
    if (pos < TCAP2) g_tlist[cell][pos] = t;
}

// ---------------------------------------------------------------------------
// Build compacted pair lists (window-pruned). Entries: (f16 K)<<16 | idx<<2,
// K = exp(-dsq/eps). SENTINEL padding. mode 1 inits ev = 1.
// ---------------------------------------------------------------------------
__global__ void build_lists(const float2* __restrict__ tlocs,
                            const float2* __restrict__ slocs)
{
    __shared__ float2 s_loc[NN];
    __shared__ unsigned short s_id[NN];
    __shared__ int s_bs[NSLAB * NXBIN + 1];       // 257 entries
    const int mode = blockIdx.z;
    const float2* row_locs = (mode ? slocs : tlocs);
    const int b = blockIdx.y;
    const int tid = threadIdx.x;
    #pragma unroll
    for (int k = 0; k < NN / THREADS; k++) {
        s_loc[tid + k * THREADS] = g_loc2[mode][b][tid + k * THREADS];
        s_id[tid + k * THREADS]  = g_id2[mode][b][tid + k * THREADS];
    }
    s_bs[tid] = g_binstart[mode][b][tid];
    if (tid == 0)
        s_bs[NSLAB * NXBIN] = g_binstart[mode][b][NSLAB * NXBIN];
    __syncthreads();

    const int wid = tid >> 5, lane = tid & 31;
    const int r = blockIdx.x * WPB + wid;
    const int g = b * NN + r;
    const float2 rl = row_locs[(size_t)b * NN + r];
    uint32_t* lp = (mode ? g_listS : g_listT) + (size_t)g * STRIDE;

    const int lo  = max((int)((rl.y - 0.2001f) * (float)NSLAB), 0);
    const int hi  = min((int)((rl.y + 0.2001f) * (float)NSLAB), NSLAB - 1);
    const int xlo = max((int)((rl.x - 0.2001f) * (float)NXBIN), 0);
    const int xhi = min((int)((rl.x + 0.2001f) * (float)NXBIN), NXBIN - 1);

    int n = 0;
    for (int s = lo; s <= hi; s++) {
        const int beg = s_bs[s * NXBIN + xlo];
        const int end = s_bs[s * NXBIN + xhi + 1];
        for (int i0 = beg; i0 < end; i0 += 32) {
            const int i = i0 + lane;
            bool pred = false;
            float dsq = 0.0f;
            unsigned short sid = 0;
            if (i < end) {
                const float2 c = s_loc[i];
                const float dx = rl.x - c.x;
                const float dy = rl.y - c.y;
                // match reference rounding: mul, mul, add (no fma contraction)
                dsq = __fadd_rn(__fmul_rn(dx, dx), __fmul_rn(dy, dy));
                pred = dsq < 0.04f;
                sid = s_id[i];
            }
            const unsigned bal = __ballot_sync(0xffffffffu, pred);
            if (pred) {
                const float K = ex2f(dsq * (-C2));   // exp(-dsq/eps)
                const unsigned short h = __half_as_ushort(__float2half(K));
                const uint32_t e = ((uint32_t)sid << 2) | ((uint32_t)h << 16);
                const int ofs = n + __popc(bal & ((1u << lane) - 1u));
                if (ofs < STRIDE) lp[ofs] = e;
            }
            n += __popc(bal);
        }
    }
    n = min(n, STRIDE);
    const int npad = min((n + 127) & ~127, STRIDE);
    for (int i = n + lane; i < npad; i += 32) lp[i] = SENTINEL;
    if (lane == 0) {
        (mode ? g_cntS : g_cntT)[g] = npad;
        if (mode) g_ev[g] = 1.0f;
    }
}

// ---------------------------------------------------------------------------
// Per-batch software barrier across PBLK co-resident blocks.
// ---------------------------------------------------------------------------
static __device__ __forceinline__ void batch_barrier(int b)
{
    __syncthreads();
    if (threadIdx.x == 0) {
        __threadfence();
        volatile int* ph = &g_phase[b];
        const int old = *ph;
        if (atomicAdd(&g_arrive[b], 1) == PBLK - 1) {
            g_arrive[b] = 0;
            __threadfence();
            *ph = old + 1;
        } else {
            int backoff = 32;
            while (*ph == old) {
                __nanosleep(backoff);
                if (backoff < 256) backoff <<= 1;
            }
        }
        __threadfence();
    }
    __syncthreads();
}

// ---------------------------------------------------------------------------
// All 16 Sinkhorn half-iterations, one persistent kernel.
// Grid (PBLK=64, BB) x 1024 threads = 256 blocks; launch_bounds(1024,2)
// guarantees 2 blocks/SM capacity -> all co-resident, occupancy ~93%.
// 2 rows/warp per half-pass; MLP-2 chunk-pair inner loop (32-reg shape).
// ---------------------------------------------------------------------------
static __device__ __forceinline__ float chunk_sum(uint4 q, const float* s_in) {
    float a;
    a  = kof(q.x) * gat(s_in, q.x);
    a  = fmaf(kof(q.y), gat(s_in, q.y), a);
    a  = fmaf(kof(q.z), gat(s_in, q.z), a);
    a  = fmaf(kof(q.w), gat(s_in, q.w), a);
    return a;
}

__global__ void __launch_bounds__(1024, 2) sinkhorn_all()
{
    __shared__ float s_in[NN];
    const int b = blockIdx.y;
    const int blk = blockIdx.x;                    // 0..PBLK-1
    const int tid = threadIdx.x, wid = tid >> 5, lane = tid & 31;
    const int rbase = blk * (NN / PBLK) + wid;     // rows rbase, rbase+32

    #pragma unroll 1
    for (int half = 0; half < 16; half++) {
        const int dir = half & 1;
        const float* vin = dir ? g_eu : g_ev;
        reinterpret_cast<float4*>(s_in)[tid] =
            reinterpret_cast<const float4*>(vin + b * NN)[tid];
        __syncthreads();

        const int* cnt = dir ? g_cntS : g_cntT;
        const uint32_t* lbase = dir ? g_listS : g_listT;
        float* vout = dir ? g_ev : g_eu;

        #pragma unroll 1
        for (int rr = 0; rr < NN / PBLK / 32; rr++) {          // 2 rows/warp
            const int g = b * NN + rbase + rr * 32;
            const int n = cnt[g];                              // <= 640
            const uint4* lp = reinterpret_cast<const uint4*>(
                lbase + (size_t)g * STRIDE);
            float acc = 0.0f;
            for (int i0 = 0; i0 < n; i0 += 256) {
                const uint4 q0 = lp[(i0 >> 2) + lane];
                const bool two = (i0 + 128) < n;
                uint4 q1;
                if (two) q1 = lp[(i0 >> 2) + 32 + lane];
                acc += chunk_sum(q0, s_in);
                if (two) acc += chunk_sum(q1, s_in);
            }
            #pragma unroll
            for (int o = 16; o; o >>= 1)
                acc += __shfl_xor_sync(0xffffffffu, acc, o);
            if (lane == 0) vout[g] = rcpf(acc);
        }
        batch_barrier(b);
    }
}

// ---------------------------------------------------------------------------
// Epilogue: one 1024-thread CTA per (2-cell superblock, batch) = 512 blocks,
// 1 CTA/SM (162KB smem). Halo V rows staged to smem PRE-SCALED by ev[s]
// (f32 read, one rounding to half2) -> inner weight is w = K * eu[t] only.
// Warp-per-target over the pooled 2-cell target list; smem (w, slot)
// broadcast; capacity overflow falls back to global f32 V * g_ev (rare,
// value-identical semantics, deterministic).
// ---------------------------------------------------------------------------
#define OFF_SLOT  0                        // short[4096]           8192
#define OFF_SRC   8192                     // ushort[VCAP]          2304
#define OFF_CNT   10496                    // int (padded)            16
#define OFF_W     10512                    // float2[32][32]        8192
#define OFF_V     18704                    // half2[VCAP][32]     147456
#define SMEM_FINAL (OFF_V + VCAP * 32 * 4) // 166160

__global__ void __launch_bounds__(1024)
final_kernel(const float* __restrict__ feats,
             const float2* __restrict__ slocs,
             float* __restrict__ out)
{
    extern __shared__ char sm[];
    short* s_slot = (short*)(sm + OFF_SLOT);
    unsigned short* s_src = (unsigned short*)(sm + OFF_SRC);
    int* s_cnt = (int*)(sm + OFF_CNT);
    float2* s_w = (float2*)(sm + OFF_W);
    __half2* s_V = (__half2*)(sm + OFF_V);

    const int b = blockIdx.y;
    const int sb = blockIdx.x;                 // 0..127 superblocks
    const int tid = threadIdx.x, wid = tid >> 5, lane = tid & 31;  // 32 warps

    #pragma unroll
    for (int k = 0; k < NN / 1024; k++) s_slot[tid + k * 1024] = -1;
    if (tid == 0) *s_cnt = 0;
    __syncthreads();

    // superblock = cells (cy, cx0) and (cy, cx0+1)
    const int cy = sb >> 3, cx0 = (sb & 7) * 2;
    const float x0 = cx0 * (1.0f / NCELL2), x1 = x0 + 2.0f / NCELL2;
    const float y0 = cy * (1.0f / NCELL2),  y1 = y0 + 1.0f / NCELL2;

    // halo membership: sources within 0.2 of the superblock bbox
    const float2* sl = slocs + (size_t)b * NN;
    for (int s = tid; s < NN; s += 1024) {
        const float2 p = sl[s];
        const float dx = fmaxf(fmaxf(x0 - p.x, p.x - x1), 0.0f);
        const float dy = fmaxf(fmaxf(y0 - p.y, p.y - y1), 0.0f);
        if (dx * dx + dy * dy < 0.0401f) {
            const int slot = atomicAdd(s_cnt, 1);
            if (slot < VCAP) { s_slot[s] = (short)slot; s_src[slot] = (unsigned short)s; }
            else s_slot[s] = -1;
        }
    }
    __syncthreads();
    const int vc = min(*s_cnt, VCAP);

    // stage V rows scaled by ev[s]: one warp per row, f32 read -> half2
    const float* Vb = feats + (size_t)b * NN * DD;
    for (int r = wid; r < vc; r += 32) {
        const int s = s_src[r];
        const float evs = g_ev[b * NN + s];
        const float2 v = *reinterpret_cast<const float2*>(
            Vb + (size_t)s * DD + lane * 2);
        s_V[r * 32 + lane] = __floats2half2_rn(v.x * evs, v.y * evs);
    }
    __syncthreads();

    // pooled targets of the 2 cells
    const int gc0 = b * NCELL2 * NCELL2 + cy * NCELL2 + cx0;
    const int tc0 = min(g_tcnt[gc0], TCAP2);
    const int tc1 = min(g_tcnt[gc0 + 1], TCAP2);
    const int tot = tc0 + tc1;

    for (int ti = wid; ti < tot; ti += 32) {
        const int t = (ti < tc0) ? g_tlist[gc0][ti] : g_tlist[gc0 + 1][ti - tc0];
        const int g = b * NN + t;
        const int n = g_cntT[g];               // multiple of 128 (or 0)
        const uint32_t* lp = g_listT + (size_t)g * STRIDE;
        const float eut = g_eu[g];

        float2 acc = make_float2(0.0f, 0.0f);
        uint32_t e = (n > 0) ? lp[lane] : SENTINEL;
        for (int i0 = 0; i0 < n; i0 += 32) {
            const float w = kof(e) * eut;              // ev folded into s_V
            const int idx = (int)((e & 0xFFFFu) >> 2);
            const int slot = (int)s_slot[idx];
            const int meta = (slot >= 0) ? slot : (-1 - idx);
            s_w[wid * 32 + lane] = make_float2(w, __int_as_float(meta));
            __syncwarp();
            if (i0 + 32 < n) e = lp[i0 + 32 + lane];   // prefetch next chunk
            #pragma unroll 8
            for (int j = 0; j < 32; j++) {
                const float2 p = s_w[wid * 32 + j];
                if (p.x != 0.0f) {   // warp-uniform; skips padding
                    const int m = __float_as_int(p.y);
                    float2 vv;
                    if (m >= 0) {
                        vv = __half22float2(s_V[m * 32 + lane]);
                    } else {          // capacity overflow (rare): global path
                        const int s = -1 - m;
                        const float evs = g_ev[b * NN + s];
                        const float2 v = *reinterpret_cast<const float2*>(
                            Vb + (size_t)s * DD + lane * 2);
                        const __half2 h = __floats2half2_rn(v.x * evs, v.y * evs);
                        vv = __half22float2(h);
                    }
                    acc.x = fmaf(p.x, vv.x, acc.x);
                    acc.y = fmaf(p.x, vv.y, acc.y);
                }
            }
            __syncwarp();
        }
        reinterpret_cast<float2*>(out)[(size_t)g * (DD / 2) + lane] = acc;
    }
}

// ---------------------------------------------------------------------------
extern "C" void kernel_launch(void* const* d_in, const int* in_sizes, int n_in,
                              void* d_out, int out_size)
{
    const float* feats  = (const float*)d_in[0];        // (b, src, 64) f32
    const float2* slocs = (const float2*)d_in[1];       // (b, src, 2)  f32
    const float2* tlocs = (const float2*)d_in[2];       // (b, tgt, 2)  f32
    float* out = (float*)d_out;                          // (b, tgt, 64) f32

    static bool attr_set = false;
    if (!attr_set) {
        cudaFuncSetAttribute(final_kernel,
                             cudaFuncAttributeMaxDynamicSharedMemorySize,
                             SMEM_FINAL);
        attr_set = true;
    }

    slab_xbin<<<dim3(BB, 2), 512>>>(tlocs, slocs);
    bin_targets<<<(BB * NN + THREADS - 1) / THREADS, THREADS>>>(tlocs);
    build_lists<<<dim3(NN / WPB, BB, 2), THREADS>>>(tlocs, slocs);
    sinkhorn_all<<<dim3(PBLK, BB), 1024>>>();
    final_kernel<<<dim3(NCELL2 * NCELL2 / 2, BB), 1024, SMEM_FINAL>>>(
        feats, slocs, out);
}

// round 13
// speedup vs baseline: 1.6298x; 1.6298x over previous
#include <cuda_runtime.h>
#include <cuda_fp16.h>
#include <cstdint>

// GeometryOptimalTransport: sparse Sinkhorn attention. b=4, n=4096, d=64.
// R13 = R11 pipeline with R12's faster sinkhorn_all dropped in.
//   setup/build: R11 (measured-good)
//   sinkhorn_all: PBLK=64, launch_bounds(1024,2), MLP-2 -> 143us measured
//   final: R11 cell-binned global-half2 version (best measured final)

#define BB 4
#define NN 4096
#define DD 64
#define STRIDE 640            // max valid neighbors ~515+6sigma; multiple of 128
#define WPB 8
#define THREADS 256
#define NSLAB 16
#define NXBIN 16
#define NCELL2 16             // 16x16 target cells for the epilogue
#define TCAP2 64              // targets per cell cap (mean 16)
#define PBLK 64               // blocks per batch in the fused pass kernel
#define SENTINEL 0u           // K = 0, off = 0 -> contributes exactly 0

// log2(e) / (EPS + 1e-8), EPS = 0.01
__device__ __constant__ float C2 = (float)(1.4426950408889634 / 0.01000001);

__device__ uint32_t g_listT[BB * NN * STRIDE];   // entries: (f16 K)<<16 | idx<<2
__device__ uint32_t g_listS[BB * NN * STRIDE];
__device__ int g_cntT[BB * NN];                  // padded counts (multiple of 128)
__device__ int g_cntS[BB * NN];
__device__ float g_eu[BB * NN];                  // 2^u
__device__ float g_ev[BB * NN];                  // 2^v
__device__ __half2 g_Vh[BB * NN * (DD / 2)];     // V in half2 (2MB)
// (yslab, xbin) sorted candidate arrays
__device__ float2 g_sortloc[2][BB][NN];
__device__ unsigned short g_sortid[2][BB][NN];
__device__ float2 g_loc2[2][BB][NN];
__device__ unsigned short g_id2[2][BB][NN];
__device__ int g_binstart[2][BB][NSLAB * NXBIN + 1];
// target cell lists for the epilogue
__device__ int g_tcnt[BB * NCELL2 * NCELL2];
__device__ int g_tlist[BB * NCELL2 * NCELL2][TCAP2];
// software barrier state (g_arrive self-resets; g_phase monotone across replays)
__device__ int g_arrive[BB];
__device__ int g_phase[BB];

static __device__ __forceinline__ float ex2f(float x) {
    float y; asm("ex2.approx.ftz.f32 %0, %1;" : "=f"(y) : "f"(x)); return y;
}
static __device__ __forceinline__ float rcpf(float x) {
    float y; asm("rcp.approx.ftz.f32 %0, %1;" : "=f"(y) : "f"(x)); return y;
}
// gather float at byte offset (entry low 16 bits hold idx*4)
static __device__ __forceinline__ float gat(const float* s, uint32_t e) {
    return *reinterpret_cast<const float*>(
        reinterpret_cast<const char*>(s) + (e & 0xFFFCu));
}
static __device__ __forceinline__ float kof(uint32_t e) {   // f16 K -> f32
    return __half2float(__ushort_as_half((unsigned short)(e >> 16)));
}

// ---------------------------------------------------------------------------
// Merged stage 1+2: y-slab counting sort, then per-slab x-bin sort.
// Deterministic (ballot compaction). Also zeroes g_tcnt.
// ---------------------------------------------------------------------------
__global__ void slab_xbin(const float2* __restrict__ tlocs,
                          const float2* __restrict__ slocs)
{
    const int b = blockIdx.x, mode = blockIdx.y;
    const float2* cl = (mode ? tlocs : slocs) + (size_t)b * NN;
    __shared__ int s_cnt[NSLAB + 1];
    const int tid = threadIdx.x, wid = tid >> 5, lane = tid & 31;  // 16 warps

    if (blockIdx.x == 0 && blockIdx.y == 0)
        for (int k = tid; k < BB * NCELL2 * NCELL2; k += 512) g_tcnt[k] = 0;

    int c = 0;
    for (int i0 = 0; i0 < NN; i0 += 32) {
        const float2 p = cl[i0 + lane];
        const int sl = min(max((int)(p.y * (float)NSLAB), 0), NSLAB - 1);
        c += __popc(__ballot_sync(0xffffffffu, sl == wid));
    }
    if (lane == 0) s_cnt[wid + 1] = c;
    __syncthreads();
    if (tid == 0) {
        s_cnt[0] = 0;
        for (int k = 1; k <= NSLAB; k++) s_cnt[k] += s_cnt[k - 1];
    }
    __syncthreads();
    {
        int base = s_cnt[wid];
        for (int i0 = 0; i0 < NN; i0 += 32) {
            const float2 p = cl[i0 + lane];
            const int sl = min(max((int)(p.y * (float)NSLAB), 0), NSLAB - 1);
            const bool m = (sl == wid);
            const unsigned bal = __ballot_sync(0xffffffffu, m);
            if (m) {
                const int o = base + __popc(bal & ((1u << lane) - 1u));
                g_sortloc[mode][b][o] = p;
                g_sortid[mode][b][o] = (unsigned short)(i0 + lane);
            }
            base += __popc(bal);
        }
    }
    __syncthreads();

    const int beg = s_cnt[wid];
    const int end = s_cnt[wid + 1];
    int base = beg;
    for (int xb = 0; xb < NXBIN; xb++) {
        if (lane == 0) g_binstart[mode][b][wid * NXBIN + xb] = base;
        for (int i0 = beg; i0 < end; i0 += 32) {
            const int i = i0 + lane;
            bool m = false;
            float2 p; unsigned short id = 0;
            if (i < end) {
                p = g_sortloc[mode][b][i];
                id = g_sortid[mode][b][i];
                const int xbin = min(max((int)(p.x * (float)NXBIN), 0), NXBIN - 1);
                m = (xbin == xb);
            }
            const unsigned bal = __ballot_sync(0xffffffffu, m);
            if (m) {
                const int o = base + __popc(bal & ((1u << lane) - 1u));
                g_loc2[mode][b][o] = p;
                g_id2[mode][b][o] = id;
            }
            base += __popc(bal);
        }
    }
    if (wid == NSLAB - 1 && lane == 0)
        g_binstart[mode][b][NSLAB * NXBIN] = end;
}

// ---------------------------------------------------------------------------
// Merged: V (f32)->half2 convert + target cell binning.
// ---------------------------------------------------------------------------
__global__ void bin_convert(const float2* __restrict__ feats2,
                            const float2* __restrict__ tlocs)
{
    const int i = blockIdx.x * THREADS + threadIdx.x;   // over BB*NN*32
    const float2 v = feats2[i];
    g_Vh[i] = __floats2half2_rn(v.x, v.y);
    if (i < BB * NN) {
        const int b = i >> 12;
        const int t = i & (NN - 1);
        const float2 p = tlocs[i];
        const int cx = min(max((int)(p.x * (float)NCELL2), 0), NCELL2 - 1);
        const int cy = min(max((int)(p.y * (float)NCELL2), 0), NCELL2 - 1);
        const int cell = b * NCELL2 * NCELL2 + cy * NCELL2 + cx;
        const int pos = atomicAdd(&g_tcnt[cell], 1);
        if (pos < TCAP2) g_tlist[cell][pos] = t;
    }
}

// ---------------------------------------------------------------------------
// Build compacted pair lists; candidates limited to the (yslab,xbin) window.
// Entries: (f16 K)<<16 | idx<<2, K = exp(-dsq/eps). SENTINEL padding to a
// multiple of 128. mode 1 also inits ev = 1.
// ---------------------------------------------------------------------------
__global__ void build_lists(const float2* __restrict__ tlocs,
                            const float2* __restrict__ slocs)
{
    __shared__ float2 s_loc[NN];
    __shared__ unsigned short s_id[NN];
    __shared__ int s_bs[NSLAB * NXBIN + 1];       // 257 entries
    const int mode = blockIdx.z;
    const float2* row_locs = (mode ? slocs : tlocs);
    const int b = blockIdx.y;
    const int tid = threadIdx.x;
    #pragma unroll
    for (int k = 0; k < NN / THREADS; k++) {
        s_loc[tid + k * THREADS] = g_loc2[mode][b][tid + k * THREADS];
        s_id[tid + k * THREADS]  = g_id2[mode][b][tid + k * THREADS];
    }
    s_bs[tid] = g_binstart[mode][b][tid];
    if (tid == 0)
        s_bs[NSLAB * NXBIN] = g_binstart[mode][b][NSLAB * NXBIN];
    __syncthreads();

    const int wid = tid >> 5, lane = tid & 31;
    const int r = blockIdx.x * WPB + wid;
    const int g = b * NN + r;
    const float2 rl = row_locs[(size_t)b * NN + r];
    uint32_t* lp = (mode ? g_listS : g_listT) + (size_t)g * STRIDE;

    const int lo  = max((int)((rl.y - 0.2001f) * (float)NSLAB), 0);
    const int hi  = min((int)((rl.y + 0.2001f) * (float)NSLAB), NSLAB - 1);
    const int xlo = max((int)((rl.x - 0.2001f) * (float)NXBIN), 0);
    const int xhi = min((int)((rl.x + 0.2001f) * (float)NXBIN), NXBIN - 1);

    int n = 0;
    for (int s = lo; s <= hi; s++) {
        const int beg = s_bs[s * NXBIN + xlo];
        const int end = s_bs[s * NXBIN + xhi + 1];
        for (int i0 = beg; i0 < end; i0 += 32) {
            const int i = i0 + lane;
            bool pred = false;
            float dsq = 0.0f;
            unsigned short sid = 0;
            if (i < end) {
                const float2 c = s_loc[i];
                const float dx = rl.x - c.x;
                const float dy = rl.y - c.y;
                // match reference rounding: mul, mul, add (no fma contraction)
                dsq = __fadd_rn(__fmul_rn(dx, dx), __fmul_rn(dy, dy));
                pred = dsq < 0.04f;
                sid = s_id[i];
            }
            const unsigned bal = __ballot_sync(0xffffffffu, pred);
            if (pred) {
                const float K = ex2f(dsq * (-C2));   // exp(-dsq/eps)
                const unsigned short h = __half_as_ushort(__float2half(K));
                const uint32_t e = ((uint32_t)sid << 2) | ((uint32_t)h << 16);
                const int ofs = n + __popc(bal & ((1u << lane) - 1u));
                if (ofs < STRIDE) lp[ofs] = e;
            }
            n += __popc(bal);
        }
    }
    n = min(n, STRIDE);
    const int npad = min((n + 127) & ~127, STRIDE);
    for (int i = n + lane; i < npad; i += 32) lp[i] = SENTINEL;
    if (lane == 0) {
        (mode ? g_cntS : g_cntT)[g] = npad;
        if (mode) g_ev[g] = 1.0f;
    }
}

// ---------------------------------------------------------------------------
// Per-batch software barrier across PBLK co-resident blocks.
// ---------------------------------------------------------------------------
static __device__ __forceinline__ void batch_barrier(int b)
{
    __syncthreads();
    if (threadIdx.x == 0) {
        __threadfence();
        volatile int* ph = &g_phase[b];
        const int old = *ph;
        if (atomicAdd(&g_arrive[b], 1) == PBLK - 1) {
            g_arrive[b] = 0;
            __threadfence();
            *ph = old + 1;
        } else {
            int backoff = 32;
            while (*ph == old) {
                __nanosleep(backoff);
                if (backoff < 256) backoff <<= 1;
            }
        }
        __threadfence();
    }
    __syncthreads();
}

// ---------------------------------------------------------------------------
// All 16 Sinkhorn half-iterations, one persistent kernel (R12-measured 143us).
// Grid (PBLK=64, BB) x 1024 threads = 256 blocks; launch_bounds(1024,2)
// guarantees 2 blocks/SM -> all co-resident, occ ~83%.
// ---------------------------------------------------------------------------
static __device__ __forceinline__ float chunk_sum(uint4 q, const float* s_in) {
    float a;
    a  = kof(q.x) * gat(s_in, q.x);
    a  = fmaf(kof(q.y), gat(s_in, q.y), a);
    a  = fmaf(kof(q.z), gat(s_in, q.z), a);
    a  = fmaf(kof(q.w), gat(s_in, q.w), a);
    return a;
}

__global__ void __launch_bounds__(1024, 2) sinkhorn_all()
{
    __shared__ float s_in[NN];
    const int b = blockIdx.y;
    const int blk = blockIdx.x;                    // 0..PBLK-1
    const int tid = threadIdx.x, wid = tid >> 5, lane = tid & 31;
    const int rbase = blk * (NN / PBLK) + wid;     // rows rbase, rbase+32

    #pragma unroll 1
    for (int half = 0; half < 16; half++) {
        const int dir = half & 1;
        const float* vin = dir ? g_eu : g_ev;
        reinterpret_cast<float4*>(s_in)[tid] =
            reinterpret_cast<const float4*>(vin + b * NN)[tid];
        __syncthreads();

        const int* cnt = dir ? g_cntS : g_cntT;
        const uint32_t* lbase = dir ? g_listS : g_listT;
        float* vout = dir ? g_ev : g_eu;

        #pragma unroll 1
        for (int rr = 0; rr < NN / PBLK / 32; rr++) {          // 2 rows/warp
            const int g = b * NN + rbase + rr * 32;
            const int n = cnt[g];                              // <= 640
            const uint4* lp = reinterpret_cast<const uint4*>(
                lbase + (size_t)g * STRIDE);
            float acc = 0.0f;
            for (int i0 = 0; i0 < n; i0 += 256) {
                const uint4 q0 = lp[(i0 >> 2) + lane];
                const bool two = (i0 + 128) < n;
                uint4 q1;
                if (two) q1 = lp[(i0 >> 2) + 32 + lane];
                acc += chunk_sum(q0, s_in);
                if (two) acc += chunk_sum(q1, s_in);
            }
            #pragma unroll
            for (int o = 16; o; o >>= 1)
                acc += __shfl_xor_sync(0xffffffffu, acc, o);
            if (lane == 0) vout[g] = rcpf(acc);
        }
        batch_barrier(b);
    }
}

// ---------------------------------------------------------------------------
// Epilogue (R11-measured-good): one CTA per (cell, batch); one warp per
// target. w = K * ev[s] * eu[t]; smem (w, off) broadcast + half2 V FMAs
// from global g_Vh (cell locality -> L1/L2 hits).
// ---------------------------------------------------------------------------
__global__ void __launch_bounds__(512)
final_kernel(float* __restrict__ out)
{
    __shared__ float s_v[NN];                  // ev for this batch
    __shared__ float2 s_w[16][32];             // (w, off-as-float) per warp
    const int b = blockIdx.y;
    const int cell = blockIdx.x;               // 0..255
    const int tid = threadIdx.x, wid = tid >> 5, lane = tid & 31;  // 16 warps

    #pragma unroll
    for (int k = 0; k < NN / 512; k++)
        s_v[tid + k * 512] = g_ev[b * NN + tid + k * 512];
    __syncthreads();

    const int gcell = b * NCELL2 * NCELL2 + cell;
    const int tcnt = min(g_tcnt[gcell], TCAP2);
    const __half2* Vb = g_Vh + (size_t)b * NN * (DD / 2);

    for (int ti = wid; ti < tcnt; ti += 16) {
        const int t = g_tlist[gcell][ti];
        const int g = b * NN + t;
        const int n = g_cntT[g];               // multiple of 128 (or 0)
        const uint32_t* lp = g_listT + (size_t)g * STRIDE;
        const float eut = g_eu[g];

        float2 acc = make_float2(0.0f, 0.0f);
        uint32_t e = (n > 0) ? lp[lane] : SENTINEL;
        for (int i0 = 0; i0 < n; i0 += 32) {
            const float w = kof(e) * gat(s_v, e) * eut;
            s_w[wid][lane] = make_float2(w, __uint_as_float(e & 0xFFFCu));
            __syncwarp();
            if (i0 + 32 < n) e = lp[i0 + 32 + lane];   // prefetch next chunk
            #pragma unroll 8
            for (int j = 0; j < 32; j++) {
                const float2 p = s_w[wid][j];
                if (p.x != 0.0f) {   // warp-uniform; skips padding/underflow
                    const float2 vv = __half22float2(
                        Vb[((size_t)__float_as_uint(p.y) << 3) + lane]);
                    acc.x = fmaf(p.x, vv.x, acc.x);
                    acc.y = fmaf(p.x, vv.y, acc.y);
                }
            }
            __syncwarp();
        }
        reinterpret_cast<float2*>(out)[(size_t)g * (DD / 2) + lane] = acc;
    }
}

// ---------------------------------------------------------------------------
extern "C" void kernel_launch(void* const* d_in, const int* in_sizes, int n_in,
                              void* d_out, int out_size)
{
    const float* feats  = (const float*)d_in[0];        // (b, src, 64) f32
    const float2* slocs = (const float2*)d_in[1];       // (b, src, 2)  f32
    const float2* tlocs = (const float2*)d_in[2];       // (b, tgt, 2)  f32
    float* out = (float*)d_out;                          // (b, tgt, 64) f32

    slab_xbin<<<dim3(BB, 2), 512>>>(tlocs, slocs);
    bin_convert<<<BB * NN * (DD / 2) / THREADS, THREADS>>>(
        (const float2*)feats, tlocs);
    build_lists<<<dim3(NN / WPB, BB, 2), THREADS>>>(tlocs, slocs);
    sinkhorn_all<<<dim3(PBLK, BB), 1024>>>();
    final_kernel<<<dim3(NCELL2 * NCELL2, BB), 512>>>(out);
}

// round 16
// speedup vs baseline: 1.7520x; 1.0750x over previous
#include <cuda_runtime.h>
#include <cuda_fp16.h>
#include <cstdint>

// GeometryOptimalTransport: sparse Sinkhorn attention. b=4, n=4096, d=64.
// R16 = third submission of the R14 design (broker infra failed twice;
//       kernel has never run). R13 + perfectly-balanced epilogue: targets
//       flattened into a cell-ordered list; final assigns exactly ONE
//       target per warp. sinkhorn_all/build/setup unchanged (attribution).

#define BB 4
#define NN 4096
#define DD 64
#define STRIDE 640            // max valid neighbors ~515+6sigma; multiple of 128
#define WPB 8
#define THREADS 256
#define NSLAB 16
#define NXBIN 16
#define NCELL2 16             // 16x16 target cells for the epilogue
#define TCAP2 64              // targets per cell cap (mean 16)
#define PBLK 64               // blocks per batch in the fused pass kernel
#define SENTINEL 0u           // K = 0, off = 0 -> contributes exactly 0

// log2(e) / (EPS + 1e-8), EPS = 0.01
__device__ __constant__ float C2 = (float)(1.4426950408889634 / 0.01000001);

__device__ uint32_t g_listT[BB * NN * STRIDE];   // entries: (f16 K)<<16 | idx<<2
__device__ uint32_t g_listS[BB * NN * STRIDE];
__device__ int g_cntT[BB * NN];                  // padded counts (multiple of 128)
__device__ int g_cntS[BB * NN];
__device__ float g_eu[BB * NN];                  // 2^u
__device__ float g_ev[BB * NN];                  // 2^v
__device__ __half2 g_Vh[BB * NN * (DD / 2)];     // V in half2 (2MB)
// (yslab, xbin) sorted candidate arrays
__device__ float2 g_sortloc[2][BB][NN];
__device__ unsigned short g_sortid[2][BB][NN];
__device__ float2 g_loc2[2][BB][NN];
__device__ unsigned short g_id2[2][BB][NN];
__device__ int g_binstart[2][BB][NSLAB * NXBIN + 1];
// target cell lists + flattened (cell-ordered) target list
__device__ int g_tcnt[BB * NCELL2 * NCELL2];
__device__ int g_tlist[BB * NCELL2 * NCELL2][TCAP2];
__device__ unsigned short g_tflat[BB * NN];
__device__ int g_ttot[BB];
// software barrier state (g_arrive self-resets; g_phase monotone across replays)
__device__ int g_arrive[BB];
__device__ int g_phase[BB];

static __device__ __forceinline__ float ex2f(float x) {
    float y; asm("ex2.approx.ftz.f32 %0, %1;" : "=f"(y) : "f"(x)); return y;
}
static __device__ __forceinline__ float rcpf(float x) {
    float y; asm("rcp.approx.ftz.f32 %0, %1;" : "=f"(y) : "f"(x)); return y;
}
// gather float at byte offset (entry low 16 bits hold idx*4)
static __device__ __forceinline__ float gat(const float* s, uint32_t e) {
    return *reinterpret_cast<const float*>(
        reinterpret_cast<const char*>(s) + (e & 0xFFFCu));
}
static __device__ __forceinline__ float kof(uint32_t e) {   // f16 K -> f32
    return __half2float(__ushort_as_half((unsigned short)(e >> 16)));
}

// ---------------------------------------------------------------------------
// Merged stage 1+2: y-slab counting sort, then per-slab x-bin sort.
// Deterministic (ballot compaction). Also zeroes g_tcnt.
// ---------------------------------------------------------------------------
__global__ void slab_xbin(const float2* __restrict__ tlocs,
                          const float2* __restrict__ slocs)
{
    const int b = blockIdx.x, mode = blockIdx.y;
    const float2* cl = (mode ? tlocs : slocs) + (size_t)b * NN;
    __shared__ int s_cnt[NSLAB + 1];
    const int tid = threadIdx.x, wid = tid >> 5, lane = tid & 31;  // 16 warps

    if (blockIdx.x == 0 && blockIdx.y == 0)
        for (int k = tid; k < BB * NCELL2 * NCELL2; k += 512) g_tcnt[k] = 0;

    int c = 0;
    for (int i0 = 0; i0 < NN; i0 += 32) {
        const float2 p = cl[i0 + lane];
        const int sl = min(max((int)(p.y * (float)NSLAB), 0), NSLAB - 1);
        c += __popc(__ballot_sync(0xffffffffu, sl == wid));
    }
    if (lane == 0) s_cnt[wid + 1] = c;
    __syncthreads();
    if (tid == 0) {
        s_cnt[0] = 0;
        for (int k = 1; k <= NSLAB; k++) s_cnt[k] += s_cnt[k - 1];
    }
    __syncthreads();
    {
        int base = s_cnt[wid];
        for (int i0 = 0; i0 < NN; i0 += 32) {
            const float2 p = cl[i0 + lane];
            const int sl = min(max((int)(p.y * (float)NSLAB), 0), NSLAB - 1);
            const bool m = (sl == wid);
            const unsigned bal = __ballot_sync(0xffffffffu, m);
            if (m) {
                const int o = base + __popc(bal & ((1u << lane) - 1u));
                g_sortloc[mode][b][o] = p;
                g_sortid[mode][b][o] = (unsigned short)(i0 + lane);
            }
            base += __popc(bal);
        }
    }
    __syncthreads();

    const int beg = s_cnt[wid];
    const int end = s_cnt[wid + 1];
    int base = beg;
    for (int xb = 0; xb < NXBIN; xb++) {
        if (lane == 0) g_binstart[mode][b][wid * NXBIN + xb] = base;
        for (int i0 = beg; i0 < end; i0 += 32) {
            const int i = i0 + lane;
            bool m = false;
            float2 p; unsigned short id = 0;
            if (i < end) {
                p = g_sortloc[mode][b][i];
                id = g_sortid[mode][b][i];
                const int xbin = min(max((int)(p.x * (float)NXBIN), 0), NXBIN - 1);
                m = (xbin == xb);
            }
            const unsigned bal = __ballot_sync(0xffffffffu, m);
            if (m) {
                const int o = base + __popc(bal & ((1u << lane) - 1u));
                g_loc2[mode][b][o] = p;
                g_id2[mode][b][o] = id;
            }
            base += __popc(bal);
        }
    }
    if (wid == NSLAB - 1 && lane == 0)
        g_binstart[mode][b][NSLAB * NXBIN] = end;
}

// ---------------------------------------------------------------------------
// Merged: V (f32)->half2 convert + target cell binning.
// ---------------------------------------------------------------------------
__global__ void bin_convert(const float2* __restrict__ feats2,
                            const float2* __restrict__ tlocs)
{
    const int i = blockIdx.x * THREADS + threadIdx.x;   // over BB*NN*32
    const float2 v = feats2[i];
    g_Vh[i] = __floats2half2_rn(v.x, v.y);
    if (i < BB * NN) {
        const int b = i >> 12;
        const int t = i & (NN - 1);
        const float2 p = tlocs[i];
        const int cx = min(max((int)(p.x * (float)NCELL2), 0), NCELL2 - 1);
        const int cy = min(max((int)(p.y * (float)NCELL2), 0), NCELL2 - 1);
        const int cell = b * NCELL2 * NCELL2 + cy * NCELL2 + cx;
        const int pos = atomicAdd(&g_tcnt[cell], 1);
        if (pos < TCAP2) g_tlist[cell][pos] = t;
    }
}

// ---------------------------------------------------------------------------
// Flatten per-cell target lists into a cell-ordered flat list (one block,
// 1024 threads; segmented Hillis-Steele scan over each batch's 256 cells).
// Within-cell order is atomic-bin order: irrelevant, targets independent.
// ---------------------------------------------------------------------------
__global__ void flatten_targets()
{
    __shared__ int s_c[BB * NCELL2 * NCELL2];   // 1024 entries
    const int tid = threadIdx.x;                // = b*256 + cell
    const int cell = tid & 255;
    const int b = tid >> 8;
    const int c = min(g_tcnt[tid], TCAP2);
    s_c[tid] = c;
    __syncthreads();
    #pragma unroll
    for (int d = 1; d < 256; d <<= 1) {
        const int add = (cell >= d) ? s_c[tid - d] : 0;
        __syncthreads();
        s_c[tid] += add;
        __syncthreads();
    }
    const int off = s_c[tid] - c;
    for (int i = 0; i < c; i++)
        g_tflat[b * NN + off + i] = (unsigned short)g_tlist[tid][i];
    if (cell == 255) g_ttot[b] = s_c[tid];
}

// ---------------------------------------------------------------------------
// Build compacted pair lists; candidates limited to the (yslab,xbin) window.
// Entries: (f16 K)<<16 | idx<<2, K = exp(-dsq/eps). SENTINEL padding to a
// multiple of 128. mode 1 also inits ev = 1.
// ---------------------------------------------------------------------------
__global__ void build_lists(const float2* __restrict__ tlocs,
                            const float2* __restrict__ slocs)
{
    __shared__ float2 s_loc[NN];
    __shared__ unsigned short s_id[NN];
    __shared__ int s_bs[NSLAB * NXBIN + 1];       // 257 entries
    const int mode = blockIdx.z;
    const float2* row_locs = (mode ? slocs : tlocs);
    const int b = blockIdx.y;
    const int tid = threadIdx.x;
    #pragma unroll
    for (int k = 0; k < NN / THREADS; k++) {
        s_loc[tid + k * THREADS] = g_loc2[mode][b][tid + k * THREADS];
        s_id[tid + k * THREADS]  = g_id2[mode][b][tid + k * THREADS];
    }
    s_bs[tid] = g_binstart[mode][b][tid];
    if (tid == 0)
        s_bs[NSLAB * NXBIN] = g_binstart[mode][b][NSLAB * NXBIN];
    __syncthreads();

    const int wid = tid >> 5, lane = tid & 31;
    const int r = blockIdx.x * WPB + wid;
    const int g = b * NN + r;
    const float2 rl = row_locs[(size_t)b * NN + r];
    uint32_t* lp = (mode ? g_listS : g_listT) + (size_t)g * STRIDE;

    const int lo  = max((int)((rl.y - 0.2001f) * (float)NSLAB), 0);
    const int hi  = min((int)((rl.y + 0.2001f) * (float)NSLAB), NSLAB - 1);
    const int xlo = max((int)((rl.x - 0.2001f) * (float)NXBIN), 0);
    const int xhi = min((int)((rl.x + 0.2001f) * (float)NXBIN), NXBIN - 1);

    int n = 0;
    for (int s = lo; s <= hi; s++) {
        const int beg = s_bs[s * NXBIN + xlo];
        const int end = s_bs[s * NXBIN + xhi + 1];
        for (int i0 = beg; i0 < end; i0 += 32) {
            const int i = i0 + lane;
            bool pred = false;
            float dsq = 0.0f;
            unsigned short sid = 0;
            if (i < end) {
                const float2 c = s_loc[i];
                const float dx = rl.x - c.x;
                const float dy = rl.y - c.y;
                // match reference rounding: mul, mul, add (no fma contraction)
                dsq = __fadd_rn(__fmul_rn(dx, dx), __fmul_rn(dy, dy));
                pred = dsq < 0.04f;
                sid = s_id[i];
            }
            const unsigned bal = __ballot_sync(0xffffffffu, pred);
            if (pred) {
                const float K = ex2f(dsq * (-C2));   // exp(-dsq/eps)
                const unsigned short h = __half_as_ushort(__float2half(K));
                const uint32_t e = ((uint32_t)sid << 2) | ((uint32_t)h << 16);
                const int ofs = n + __popc(bal & ((1u << lane) - 1u));
                if (ofs < STRIDE) lp[ofs] = e;
            }
            n += __popc(bal);
        }
    }
    n = min(n, STRIDE);
    const int npad = min((n + 127) & ~127, STRIDE);
    for (int i = n + lane; i < npad; i += 32) lp[i] = SENTINEL;
    if (lane == 0) {
        (mode ? g_cntS : g_cntT)[g] = npad;
        if (mode) g_ev[g] = 1.0f;
    }
}

// ---------------------------------------------------------------------------
// Per-batch software barrier across PBLK co-resident blocks.
// ---------------------------------------------------------------------------
static __device__ __forceinline__ void batch_barrier(int b)
{
    __syncthreads();
    if (threadIdx.x == 0) {
        __threadfence();
        volatile int* ph = &g_phase[b];
        const int old = *ph;
        if (atomicAdd(&g_arrive[b], 1) == PBLK - 1) {
            g_arrive[b] = 0;
            __threadfence();
            *ph = old + 1;
        } else {
            int backoff = 32;
            while (*ph == old) {
                __nanosleep(backoff);
                if (backoff < 256) backoff <<= 1;
            }
        }
        __threadfence();
    }
    __syncthreads();
}

// ---------------------------------------------------------------------------
// All 16 Sinkhorn half-iterations, one persistent kernel (measured 142us).
// Grid (PBLK=64, BB) x 1024 threads = 256 blocks; launch_bounds(1024,2)
// guarantees 2 blocks/SM -> all co-resident, occ ~84%.
// ---------------------------------------------------------------------------
static __device__ __forceinline__ float chunk_sum(uint4 q, const float* s_in) {
    float a;
    a  = kof(q.x) * gat(s_in, q.x);
    a  = fmaf(kof(q.y), gat(s_in, q.y), a);
    a  = fmaf(kof(q.z), gat(s_in, q.z), a);
    a  = fmaf(kof(q.w), gat(s_in, q.w), a);
    return a;
}

__global__ void __launch_bounds__(1024, 2) sinkhorn_all()
{
    __shared__ float s_in[NN];
    const int b = blockIdx.y;
    const int blk = blockIdx.x;                    // 0..PBLK-1
    const int tid = threadIdx.x, wid = tid >> 5, lane = tid & 31;
    const int rbase = blk * (NN / PBLK) + wid;     // rows rbase, rbase+32

    #pragma unroll 1
    for (int half = 0; half < 16; half++) {
        const int dir = half & 1;
        const float* vin = dir ? g_eu : g_ev;
        reinterpret_cast<float4*>(s_in)[tid] =
            reinterpret_cast<const float4*>(vin + b * NN)[tid];
        __syncthreads();

        const int* cnt = dir ? g_cntS : g_cntT;
        const uint32_t* lbase = dir ? g_listS : g_listT;
        float* vout = dir ? g_ev : g_eu;

        #pragma unroll 1
        for (int rr = 0; rr < NN / PBLK / 32; rr++) {          // 2 rows/warp
            const int g = b * NN + rbase + rr * 32;
            const int n = cnt[g];                              // <= 640
            const uint4* lp = reinterpret_cast<const uint4*>(
                lbase + (size_t)g * STRIDE);
            float acc = 0.0f;
            for (int i0 = 0; i0 < n; i0 += 256) {
                const uint4 q0 = lp[(i0 >> 2) + lane];
                const bool two = (i0 + 128) < n;
                uint4 q1;
                if (two) q1 = lp[(i0 >> 2) + 32 + lane];
                acc += chunk_sum(q0, s_in);
                if (two) acc += chunk_sum(q1, s_in);
            }
            #pragma unroll
            for (int o = 16; o; o >>= 1)
                acc += __shfl_xor_sync(0xffffffffu, acc, o);
            if (lane == 0) vout[g] = rcpf(acc);
        }
        batch_barrier(b);
    }
}

// ---------------------------------------------------------------------------
// Epilogue v2: ONE target per warp via the flat cell-ordered list -> perfect
// balance; adjacent warps share a cell's V halo (L1/L2 locality).
// w = K * ev[s] * eu[t]; smem (w, off) broadcast + half2 V FMAs from g_Vh.
// ---------------------------------------------------------------------------
__global__ void __launch_bounds__(512)
final_kernel(float* __restrict__ out)
{
    __shared__ float s_v[NN];                  // ev for this batch
    __shared__ float2 s_w[16][32];             // (w, off-as-float) per warp
    const int b = blockIdx.y;
    const int tid = threadIdx.x, wid = tid >> 5, lane = tid & 31;  // 16 warps

    #pragma unroll
    for (int k = 0; k < NN / 512; k++)
        s_v[tid + k * 512] = g_ev[b * NN + tid + k * 512];
    __syncthreads();

    const int ti = blockIdx.x * 16 + wid;      // flat target index, 0..4095
    if (ti >= g_ttot[b]) return;               // (cap overflow guard; never hit)
    const int t = g_tflat[b * NN + ti];
    const int g = b * NN + t;
    const int n = g_cntT[g];                   // multiple of 128 (or 0)
    const uint32_t* lp = g_listT + (size_t)g * STRIDE;
    const float eut = g_eu[g];
    const __half2* Vb = g_Vh + (size_t)b * NN * (DD / 2);

    float2 acc = make_float2(0.0f, 0.0f);
    uint32_t e = (n > 0) ? lp[lane] : SENTINEL;
    for (int i0 = 0; i0 < n; i0 += 32) {
        const float w = kof(e) * gat(s_v, e) * eut;
        s_w[wid][lane] = make_float2(w, __uint_as_float(e & 0xFFFCu));
        __syncwarp();
        if (i0 + 32 < n) e = lp[i0 + 32 + lane];       // prefetch next chunk
        #pragma unroll 8
        for (int j = 0; j < 32; j++) {
            const float2 p = s_w[wid][j];
            if (p.x != 0.0f) {   // warp-uniform; skips padding/underflow
                const float2 vv = __half22float2(
                    Vb[((size_t)__float_as_uint(p.y) << 3) + lane]);
                acc.x = fmaf(p.x, vv.x, acc.x);
                acc.y = fmaf(p.x, vv.y, acc.y);
            }
        }
        __syncwarp();
    }
    reinterpret_cast<float2*>(out)[(size_t)g * (DD / 2) + lane] = acc;
}

// ---------------------------------------------------------------------------
extern "C" void kernel_launch(void* const* d_in, const int* in_sizes, int n_in,
                              void* d_out, int out_size)
{
    const float* feats  = (const float*)d_in[0];        // (b, src, 64) f32
    const float2* slocs = (const float2*)d_in[1];       // (b, src, 2)  f32
    const float2* tlocs = (const float2*)d_in[2];       // (b, tgt, 2)  f32
    float* out = (float*)d_out;                          // (b, tgt, 64) f32

    slab_xbin<<<dim3(BB, 2), 512>>>(tlocs, slocs);
    bin_convert<<<BB * NN * (DD / 2) / THREADS, THREADS>>>(
        (const float2*)feats, tlocs);
    flatten_targets<<<1, 1024>>>();
    build_lists<<<dim3(NN / WPB, BB, 2), THREADS>>>(tlocs, slocs);
    sinkhorn_all<<<dim3(PBLK, BB), 1024>>>();
    final_kernel<<<dim3(NN / 16, BB), 512>>>(out);
}

// round 17
// speedup vs baseline: 1.8510x; 1.0565x over previous
#include <cuda_runtime.h>
#include <cuda_fp16.h>
#include <cstdint>

// GeometryOptimalTransport: sparse Sinkhorn attention. b=4, n=4096, d=64.
// R17 = R16 + (1) build_lists: drop s_id smem (global id gather on valid
//       only) -> 33KB smem, 6 blocks/SM, occ 49->75%;
//       (2) final: true-count loops (no sentinel iterations, no w!=0
//       branch) + ragged tail. Identical math -> identical rel_err.

#define BB 4
#define NN 4096
#define DD 64
#define STRIDE 640            // max valid neighbors ~515+6sigma; multiple of 128
#define WPB 8
#define THREADS 256
#define NSLAB 16
#define NXBIN 16
#define NCELL2 16             // 16x16 target cells for the epilogue
#define TCAP2 64              // targets per cell cap (mean 16)
#define PBLK 64               // blocks per batch in the fused pass kernel
#define SENTINEL 0u           // K = 0, off = 0 -> contributes exactly 0

// log2(e) / (EPS + 1e-8), EPS = 0.01
__device__ __constant__ float C2 = (float)(1.4426950408889634 / 0.01000001);

__device__ uint32_t g_listT[BB * NN * STRIDE];   // entries: (f16 K)<<16 | idx<<2
__device__ uint32_t g_listS[BB * NN * STRIDE];
__device__ int g_cntT[BB * NN];                  // padded counts (multiple of 128)
__device__ int g_cntS[BB * NN];
__device__ int g_cntR[BB * NN];                  // REAL count for listT (final)
__device__ float g_eu[BB * NN];                  // 2^u
__device__ float g_ev[BB * NN];                  // 2^v
__device__ __half2 g_Vh[BB * NN * (DD / 2)];     // V in half2 (2MB)
// (yslab, xbin) sorted candidate arrays
__device__ float2 g_sortloc[2][BB][NN];
__device__ unsigned short g_sortid[2][BB][NN];
__device__ float2 g_loc2[2][BB][NN];
__device__ unsigned short g_id2[2][BB][NN];
__device__ int g_binstart[2][BB][NSLAB * NXBIN + 1];
// target cell lists + flattened (cell-ordered) target list
__device__ int g_tcnt[BB * NCELL2 * NCELL2];
__device__ int g_tlist[BB * NCELL2 * NCELL2][TCAP2];
__device__ unsigned short g_tflat[BB * NN];
__device__ int g_ttot[BB];
// software barrier state (g_arrive self-resets; g_phase monotone across replays)
__device__ int g_arrive[BB];
__device__ int g_phase[BB];

static __device__ __forceinline__ float ex2f(float x) {
    float y; asm("ex2.approx.ftz.f32 %0, %1;" : "=f"(y) : "f"(x)); return y;
}
static __device__ __forceinline__ float rcpf(float x) {
    float y; asm("rcp.approx.ftz.f32 %0, %1;" : "=f"(y) : "f"(x)); return y;
}
// gather float at byte offset (entry low 16 bits hold idx*4)
static __device__ __forceinline__ float gat(const float* s, uint32_t e) {
    return *reinterpret_cast<const float*>(
        reinterpret_cast<const char*>(s) + (e & 0xFFFCu));
}
static __device__ __forceinline__ float kof(uint32_t e) {   // f16 K -> f32
    return __half2float(__ushort_as_half((unsigned short)(e >> 16)));
}

// ---------------------------------------------------------------------------
// Merged stage 1+2: y-slab counting sort, then per-slab x-bin sort.
// Deterministic (ballot compaction). Also zeroes g_tcnt.
// ---------------------------------------------------------------------------
__global__ void slab_xbin(const float2* __restrict__ tlocs,
                          const float2* __restrict__ slocs)
{
    const int b = blockIdx.x, mode = blockIdx.y;
    const float2* cl = (mode ? tlocs : slocs) + (size_t)b * NN;
    __shared__ int s_cnt[NSLAB + 1];
    const int tid = threadIdx.x, wid = tid >> 5, lane = tid & 31;  // 16 warps

    if (blockIdx.x == 0 && blockIdx.y == 0)
        for (int k = tid; k < BB * NCELL2 * NCELL2; k += 512) g_tcnt[k] = 0;

    int c = 0;
    for (int i0 = 0; i0 < NN; i0 += 32) {
        const float2 p = cl[i0 + lane];
        const int sl = min(max((int)(p.y * (float)NSLAB), 0), NSLAB - 1);
        c += __popc(__ballot_sync(0xffffffffu, sl == wid));
    }
    if (lane == 0) s_cnt[wid + 1] = c;
    __syncthreads();
    if (tid == 0) {
        s_cnt[0] = 0;
        for (int k = 1; k <= NSLAB; k++) s_cnt[k] += s_cnt[k - 1];
    }
    __syncthreads();
    {
        int base = s_cnt[wid];
        for (int i0 = 0; i0 < NN; i0 += 32) {
            const float2 p = cl[i0 + lane];
            const int sl = min(max((int)(p.y * (float)NSLAB), 0), NSLAB - 1);
            const bool m = (sl == wid);
            const unsigned bal = __ballot_sync(0xffffffffu, m);
            if (m) {
                const int o = base + __popc(bal & ((1u << lane) - 1u));
                g_sortloc[mode][b][o] = p;
                g_sortid[mode][b][o] = (unsigned short)(i0 + lane);
            }
            base += __popc(bal);
        }
    }
    __syncthreads();

    const int beg = s_cnt[wid];
    const int end = s_cnt[wid + 1];
    int base = beg;
    for (int xb = 0; xb < NXBIN; xb++) {
        if (lane == 0) g_binstart[mode][b][wid * NXBIN + xb] = base;
        for (int i0 = beg; i0 < end; i0 += 32) {
            const int i = i0 + lane;
            bool m = false;
            float2 p; unsigned short id = 0;
            if (i < end) {
                p = g_sortloc[mode][b][i];
                id = g_sortid[mode][b][i];
                const int xbin = min(max((int)(p.x * (float)NXBIN), 0), NXBIN - 1);
                m = (xbin == xb);
            }
            const unsigned bal = __ballot_sync(0xffffffffu, m);
            if (m) {
                const int o = base + __popc(bal & ((1u << lane) - 1u));
                g_loc2[mode][b][o] = p;
                g_id2[mode][b][o] = id;
            }
            base += __popc(bal);
        }
    }
    if (wid == NSLAB - 1 && lane == 0)
        g_binstart[mode][b][NSLAB * NXBIN] = end;
}

// ---------------------------------------------------------------------------
// Merged: V (f32)->half2 convert + target cell binning.
// ---------------------------------------------------------------------------
__global__ void bin_convert(const float2* __restrict__ feats2,
                            const float2* __restrict__ tlocs)
{
    const int i = blockIdx.x * THREADS + threadIdx.x;   // over BB*NN*32
    const float2 v = feats2[i];
    g_Vh[i] = __floats2half2_rn(v.x, v.y);
    if (i < BB * NN) {
        const int b = i >> 12;
        const int t = i & (NN - 1);
        const float2 p = tlocs[i];
        const int cx = min(max((int)(p.x * (float)NCELL2), 0), NCELL2 - 1);
        const int cy = min(max((int)(p.y * (float)NCELL2), 0), NCELL2 - 1);
        const int cell = b * NCELL2 * NCELL2 + cy * NCELL2 + cx;
        const int pos = atomicAdd(&g_tcnt[cell], 1);
        if (pos < TCAP2) g_tlist[cell][pos] = t;
    }
}

// ---------------------------------------------------------------------------
// Flatten per-cell target lists into a cell-ordered flat list (one block,
// 1024 threads; segmented Hillis-Steele scan over each batch's 256 cells).
// ---------------------------------------------------------------------------
__global__ void flatten_targets()
{
    __shared__ int s_c[BB * NCELL2 * NCELL2];   // 1024 entries
    const int tid = threadIdx.x;                // = b*256 + cell
    const int cell = tid & 255;
    const int b = tid >> 8;
    const int c = min(g_tcnt[tid], TCAP2);
    s_c[tid] = c;
    __syncthreads();
    #pragma unroll
    for (int d = 1; d < 256; d <<= 1) {
        const int add = (cell >= d) ? s_c[tid - d] : 0;
        __syncthreads();
        s_c[tid] += add;
        __syncthreads();
    }
    const int off = s_c[tid] - c;
    for (int i = 0; i < c; i++)
        g_tflat[b * NN + off + i] = (unsigned short)g_tlist[tid][i];
    if (cell == 255) g_ttot[b] = s_c[tid];
}

// ---------------------------------------------------------------------------
// Build compacted pair lists; candidates limited to the (yslab,xbin) window.
// Entries: (f16 K)<<16 | idx<<2, K = exp(-dsq/eps). SENTINEL padding to a
// multiple of 128. mode 1 also inits ev = 1. Writes real count (g_cntR) for
// the final kernel. Only s_loc + s_bs staged (33KB smem -> 6 blocks/SM);
// ids gathered from global for the ~30% valid candidates.
// ---------------------------------------------------------------------------
__global__ void build_lists(const float2* __restrict__ tlocs,
                            const float2* __restrict__ slocs)
{
    __shared__ float2 s_loc[NN];
    __shared__ int s_bs[NSLAB * NXBIN + 1];       // 257 entries
    const int mode = blockIdx.z;
    const float2* row_locs = (mode ? slocs : tlocs);
    const int b = blockIdx.y;
    const int tid = threadIdx.x;
    #pragma unroll
    for (int k = 0; k < NN / THREADS; k++)
        s_loc[tid + k * THREADS] = g_loc2[mode][b][tid + k * THREADS];
    s_bs[tid] = g_binstart[mode][b][tid];
    if (tid == 0)
        s_bs[NSLAB * NXBIN] = g_binstart[mode][b][NSLAB * NXBIN];
    __syncthreads();

    const int wid = tid >> 5, lane = tid & 31;
    const int r = blockIdx.x * WPB + wid;
    const int g = b * NN + r;
    const float2 rl = row_locs[(size_t)b * NN + r];
    uint32_t* lp = (mode ? g_listS : g_listT) + (size_t)g * STRIDE;
    const unsigned short* idp = g_id2[mode][b];

    const int lo  = max((int)((rl.y - 0.2001f) * (float)NSLAB), 0);
    const int hi  = min((int)((rl.y + 0.2001f) * (float)NSLAB), NSLAB - 1);
    const int xlo = max((int)((rl.x - 0.2001f) * (float)NXBIN), 0);
    const int xhi = min((int)((rl.x + 0.2001f) * (float)NXBIN), NXBIN - 1);

    int n = 0;
    for (int s = lo; s <= hi; s++) {
        const int beg = s_bs[s * NXBIN + xlo];
        const int end = s_bs[s * NXBIN + xhi + 1];
        for (int i0 = beg; i0 < end; i0 += 32) {
            const int i = i0 + lane;
            bool pred = false;
            float dsq = 0.0f;
            if (i < end) {
                const float2 c = s_loc[i];
                const float dx = rl.x - c.x;
                const float dy = rl.y - c.y;
                // match reference rounding: mul, mul, add (no fma contraction)
                dsq = __fadd_rn(__fmul_rn(dx, dx), __fmul_rn(dy, dy));
                pred = dsq < 0.04f;
            }
            const unsigned bal = __ballot_sync(0xffffffffu, pred);
            if (pred) {
                const unsigned short sid = __ldg(idp + i);   // valid-only gather
                const float K = ex2f(dsq * (-C2));   // exp(-dsq/eps)
                const unsigned short h = __half_as_ushort(__float2half(K));
                const uint32_t e = ((uint32_t)sid << 2) | ((uint32_t)h << 16);
                const int ofs = n + __popc(bal & ((1u << lane) - 1u));
                if (ofs < STRIDE) lp[ofs] = e;
            }
            n += __popc(bal);
        }
    }
    n = min(n, STRIDE);
    const int npad = min((n + 127) & ~127, STRIDE);
    for (int i = n + lane; i < npad; i += 32) lp[i] = SENTINEL;
    if (lane == 0) {
        (mode ? g_cntS : g_cntT)[g] = npad;
        if (!mode) g_cntR[g] = n;
        if (mode) g_ev[g] = 1.0f;
    }
}

// ---------------------------------------------------------------------------
// Per-batch software barrier across PBLK co-resident blocks.
// ---------------------------------------------------------------------------
static __device__ __forceinline__ void batch_barrier(int b)
{
    __syncthreads();
    if (threadIdx.x == 0) {
        __threadfence();
        volatile int* ph = &g_phase[b];
        const int old = *ph;
        if (atomicAdd(&g_arrive[b], 1) == PBLK - 1) {
            g_arrive[b] = 0;
            __threadfence();
            *ph = old + 1;
        } else {
            int backoff = 32;
            while (*ph == old) {
                __nanosleep(backoff);
                if (backoff < 256) backoff <<= 1;
            }
        }
        __threadfence();
    }
    __syncthreads();
}

// ---------------------------------------------------------------------------
// All 16 Sinkhorn half-iterations, one persistent kernel (measured 142us).
// ---------------------------------------------------------------------------
static __device__ __forceinline__ float chunk_sum(uint4 q, const float* s_in) {
    float a;
    a  = kof(q.x) * gat(s_in, q.x);
    a  = fmaf(kof(q.y), gat(s_in, q.y), a);
    a  = fmaf(kof(q.z), gat(s_in, q.z), a);
    a  = fmaf(kof(q.w), gat(s_in, q.w), a);
    return a;
}

__global__ void __launch_bounds__(1024, 2) sinkhorn_all()
{
    __shared__ float s_in[NN];
    const int b = blockIdx.y;
    const int blk = blockIdx.x;                    // 0..PBLK-1
    const int tid = threadIdx.x, wid = tid >> 5, lane = tid & 31;
    const int rbase = blk * (NN / PBLK) + wid;     // rows rbase, rbase+32

    #pragma unroll 1
    for (int half = 0; half < 16; half++) {
        const int dir = half & 1;
        const float* vin = dir ? g_eu : g_ev;
        reinterpret_cast<float4*>(s_in)[tid] =
            reinterpret_cast<const float4*>(vin + b * NN)[tid];
        __syncthreads();

        const int* cnt = dir ? g_cntS : g_cntT;
        const uint32_t* lbase = dir ? g_listS : g_listT;
        float* vout = dir ? g_ev : g_eu;

        #pragma unroll 1
        for (int rr = 0; rr < NN / PBLK / 32; rr++) {          // 2 rows/warp
            const int g = b * NN + rbase + rr * 32;
            const int n = cnt[g];                              // <= 640
            const uint4* lp = reinterpret_cast<const uint4*>(
                lbase + (size_t)g * STRIDE);
            float acc = 0.0f;
            for (int i0 = 0; i0 < n; i0 += 256) {
                const uint4 q0 = lp[(i0 >> 2) + lane];
                const bool two = (i0 + 128) < n;
                uint4 q1;
                if (two) q1 = lp[(i0 >> 2) + 32 + lane];
                acc += chunk_sum(q0, s_in);
                if (two) acc += chunk_sum(q1, s_in);
            }
            #pragma unroll
            for (int o = 16; o; o >>= 1)
                acc += __shfl_xor_sync(0xffffffffu, acc, o);
            if (lane == 0) vout[g] = rcpf(acc);
        }
        batch_barrier(b);
    }
}

// ---------------------------------------------------------------------------
// Epilogue v3: one target per warp (flat cell-ordered list); TRUE-count
// loops: full 32-wide chunks are branch-free (all entries real -> w > 0),
// ragged tail bounded by nr - i0. Sentinel work eliminated.
// ---------------------------------------------------------------------------
__global__ void __launch_bounds__(512)
final_kernel(float* __restrict__ out)
{
    __shared__ float s_v[NN];                  // ev for this batch
    __shared__ float2 s_w[16][32];             // (w, off-as-float) per warp
    const int b = blockIdx.y;
    const int tid = threadIdx.x, wid = tid >> 5, lane = tid & 31;  // 16 warps

    #pragma unroll
    for (int k = 0; k < NN / 512; k++)
        s_v[tid + k * 512] = g_ev[b * NN + tid + k * 512];
    __syncthreads();

    const int ti = blockIdx.x * 16 + wid;      // flat target index, 0..4095
    if (ti >= g_ttot[b]) return;               // (cap overflow guard; never hit)
    const int t = g_tflat[b * NN + ti];
    const int g = b * NN + t;
    const int nr = g_cntR[g];                  // real count
    const uint32_t* lp = g_listT + (size_t)g * STRIDE;
    const float eut = g_eu[g];
    const __half2* Vb = g_Vh + (size_t)b * NN * (DD / 2);

    float2 acc = make_float2(0.0f, 0.0f);
    uint32_t e = (nr > 0) ? lp[lane] : SENTINEL;
    int i0 = 0;
    // full chunks: 32 real entries, no per-j guard
    for (; i0 + 32 <= nr; i0 += 32) {
        const float w = kof(e) * gat(s_v, e) * eut;
        s_w[wid][lane] = make_float2(w, __uint_as_float(e & 0xFFFCu));
        __syncwarp();
        if (i0 + 32 < nr) e = lp[i0 + 32 + lane];  // within padded region (safe)
        #pragma unroll 8
        for (int j = 0; j < 32; j++) {
            const float2 p = s_w[wid][j];
            const float2 vv = __half22float2(
                Vb[((size_t)__float_as_uint(p.y) << 3) + lane]);
            acc.x = fmaf(p.x, vv.x, acc.x);
            acc.y = fmaf(p.x, vv.y, acc.y);
        }
        __syncwarp();
    }
    // ragged tail (entries beyond nr are sentinel; never read below)
    if (i0 < nr) {
        const float w = kof(e) * gat(s_v, e) * eut;
        s_w[wid][lane] = make_float2(w, __uint_as_float(e & 0xFFFCu));
        __syncwarp();
        const int jmax = nr - i0;
        for (int j = 0; j < jmax; j++) {
            const float2 p = s_w[wid][j];
            const float2 vv = __half22float2(
                Vb[((size_t)__float_as_uint(p.y) << 3) + lane]);
            acc.x = fmaf(p.x, vv.x, acc.x);
            acc.y = fmaf(p.x, vv.y, acc.y);
        }
    }
    reinterpret_cast<float2*>(out)[(size_t)g * (DD / 2) + lane] = acc;
}

// ---------------------------------------------------------------------------
extern "C" void kernel_launch(void* const* d_in, const int* in_sizes, int n_in,
                              void* d_out, int out_size)
{
    const float* feats  = (const float*)d_in[0];        // (b, src, 64) f32
    const float2* slocs = (const float2*)d_in[1];       // (b, src, 2)  f32
    const float2* tlocs = (const float2*)d_in[2];       // (b, tgt, 2)  f32
    float* out = (float*)d_out;                          // (b, tgt, 64) f32

    slab_xbin<<<dim3(BB, 2), 512>>>(tlocs, slocs);
    bin_convert<<<BB * NN * (DD / 2) / THREADS, THREADS>>>(
        (const float2*)feats, tlocs);
    flatten_targets<<<1, 1024>>>();
    build_lists<<<dim3(NN / WPB, BB, 2), THREADS>>>(tlocs, slocs);
    sinkhorn_all<<<dim3(PBLK, BB), 1024>>>();
    final_kernel<<<dim3(NN / 16, BB), 512>>>(out);
}